// round 1
// baseline (speedup 1.0000x reference)
#include <cuda_runtime.h>

// Guided attention loss: out = sum_{b,i,j} aln[b,i,j] * w(b,i,j) / B
// w = 1 - exp(-(i - j/Ti*To)^2 / (2*sigma^2)), zero outside (i<To, j<Ti).
// Pure HBM-streaming reduction; 262 MB read (less with row skipping).

#define B_DIM   64
#define T_OUT   2000
#define T_IN    512
#define ROWS    (B_DIM * T_OUT)
#define INV2S2  3.125f   // 1/(2*0.4^2)

__device__ double g_acc;

__global__ void gal_init() { g_acc = 0.0; }

__global__ __launch_bounds__(128) void gal_main(
    const float4* __restrict__ aln,
    const int*    __restrict__ ilen,
    const int*    __restrict__ olen)
{
    const int lane = threadIdx.x;              // 0..127, one float4 per row
    const int jbase = lane * 4;
    float acc = 0.0f;

    for (int row = blockIdx.x; row < ROWS; row += gridDim.x) {
        const int b = row / T_OUT;
        const int i = row - b * T_OUT;
        const int To = __ldg(&olen[b]);
        if (i >= To) continue;                 // whole row zero: skip the load
        const int Ti = __ldg(&ilen[b]);

        const float4 a = aln[(size_t)row * (T_IN / 4) + lane];
        const float Tif = (float)Ti;
        const float Tof = (float)To;
        const float fi  = (float)i;

        const float av[4] = {a.x, a.y, a.z, a.w};
        #pragma unroll
        for (int k = 0; k < 4; ++k) {
            const int j = jbase + k;
            if (j < Ti) {
                const float ej = (float)j / Tif * Tof;   // match ref ordering
                const float d  = fi - ej;
                const float w  = 1.0f - __expf(-(d * d) * INV2S2);
                acc += av[k] * w;
            }
        }
    }

    // warp reduce
    #pragma unroll
    for (int off = 16; off > 0; off >>= 1)
        acc += __shfl_down_sync(0xFFFFFFFFu, acc, off);

    __shared__ float warp_sums[4];
    const int wid = threadIdx.x >> 5;
    if ((threadIdx.x & 31) == 0) warp_sums[wid] = acc;
    __syncthreads();

    if (threadIdx.x == 0) {
        float s = warp_sums[0] + warp_sums[1] + warp_sums[2] + warp_sums[3];
        atomicAdd(&g_acc, (double)s);
    }
}

__global__ void gal_final(float* out) {
    out[0] = (float)(g_acc / (double)B_DIM);
}

extern "C" void kernel_launch(void* const* d_in, const int* in_sizes, int n_in,
                              void* d_out, int out_size)
{
    const float4* aln = (const float4*)d_in[0];
    const int*    ilen = (const int*)d_in[1];
    const int*    olen = (const int*)d_in[2];
    float* out = (float*)d_out;

    gal_init<<<1, 1>>>();
    gal_main<<<2368, 128>>>(aln, ilen, olen);   // 148 SMs * 16
    gal_final<<<1, 1>>>(out);
}

// round 2
// speedup vs baseline: 2.4817x; 2.4817x over previous
#include <cuda_runtime.h>

// Guided attention loss: out = sum_{b,i,j} aln[b,i,j] * w(b,i,j) / B
// w = 1 - exp(-(i - j/Ti*To)^2 / (2*sigma^2)), zero for i>=To or j>=Ti.
//
// Layout trick: block = i (0..1999), thread = j-chunk (128 float4s), batch b
// is the loop variable -> zero integer divisions, lengths cached in smem.
// 4 independent predicated LDG.128 per iteration (MLP_p1=4); loads for
// invalid (row/chunk) regions are never issued -> ~147MB effective traffic.

#define B_DIM   64
#define T_OUT   2000
#define T_IN    512
#define NEG_INV2S2 (-3.125f)   // -1/(2*0.4^2)

__device__ double g_acc;   // zero at module load; final kernel resets each call

__global__ __launch_bounds__(128) void gal_main(
    const float4* __restrict__ aln,
    const int*    __restrict__ ilen,
    const int*    __restrict__ olen)
{
    __shared__ float sTo[B_DIM];   // output_lengths  (as float, exact)
    __shared__ float sTi[B_DIM];   // input_lengths
    __shared__ float sR [B_DIM];   // To/Ti

    const int t = threadIdx.x;     // 0..127
    if (t < B_DIM)            sTo[t]         = (float)olen[t];
    else if (t < 2 * B_DIM)   sTi[t - B_DIM] = (float)ilen[t - B_DIM];
    __syncthreads();
    if (t < B_DIM) sR[t] = __fdividef(sTo[t], sTi[t]);
    __syncthreads();

    const int   i  = blockIdx.x;          // output position, constant per block
    const float fi = (float)i;
    const float jb = (float)(t * 4);      // first j this thread owns
    float acc = 0.0f;

    // base address of (b=0, i) row chunk for this thread
    const float4* p0 = aln + ((size_t)i * (T_IN / 4)) + t;
    const size_t  bstride = (size_t)T_OUT * (T_IN / 4);   // float4s per batch

    #pragma unroll 1
    for (int it = 0; it < B_DIM; it += 4) {
        float4 a[4];
        bool   pr[4];
        // ---- front-batched independent loads (MLP=4) ----
        #pragma unroll
        for (int k = 0; k < 4; ++k) {
            const int b = it + k;
            pr[k] = (fi < sTo[b]) & (jb < sTi[b]);
            a[k] = make_float4(0.f, 0.f, 0.f, 0.f);
            if (pr[k]) a[k] = p0[(size_t)b * bstride];
        }
        // ---- compute ----
        #pragma unroll
        for (int k = 0; k < 4; ++k) {
            if (!pr[k]) continue;
            const int   b   = it + k;
            const float Tif = sTi[b];
            const float r   = sR[b];
            const float av[4] = {a[k].x, a[k].y, a[k].z, a[k].w};
            #pragma unroll
            for (int kk = 0; kk < 4; ++kk) {
                const float jf = jb + (float)kk;
                if (jf < Tif) {
                    const float d = fi - jf * r;
                    const float e = __expf(d * d * NEG_INV2S2);
                    acc += av[kk] - av[kk] * e;   // a*(1-e)
                }
            }
        }
    }

    // block reduce
    #pragma unroll
    for (int off = 16; off > 0; off >>= 1)
        acc += __shfl_down_sync(0xFFFFFFFFu, acc, off);

    __shared__ float ws[4];
    if ((t & 31) == 0) ws[t >> 5] = acc;
    __syncthreads();
    if (t == 0)
        atomicAdd(&g_acc, (double)(ws[0] + ws[1] + ws[2] + ws[3]));
}

__global__ void gal_final(float* out) {
    out[0] = (float)(g_acc / (double)B_DIM);
    g_acc = 0.0;   // reset for next graph replay (deterministic)
}

extern "C" void kernel_launch(void* const* d_in, const int* in_sizes, int n_in,
                              void* d_out, int out_size)
{
    const float4* aln  = (const float4*)d_in[0];
    const int*    ilen = (const int*)d_in[1];
    const int*    olen = (const int*)d_in[2];

    gal_main<<<T_OUT, 128>>>(aln, ilen, olen);
    gal_final<<<1, 1>>>((float*)d_out);
}